// round 15
// baseline (speedup 1.0000x reference)
#include <cuda_runtime.h>
#include <cuda_bf16.h>
#include <cuda_fp16.h>
#include <cstdint>

// Problem constants
#define B_ 2
#define S_ 2048
#define E_ 2048
#define H_ 16
#define D_ 128
#define MROWS (B_ * S_)   // 4096
#define ME ((size_t)MROWS * E_)
#define EE ((size_t)E_ * E_)

// 1/sqrt(128) * log2(e)  — folded into Q projection output
#define QSCALE 0.12752262159188963f

// ---------------------------------------------------------------------------
// Scratch (no cudaMalloc allowed) — fp16 everywhere
// ---------------------------------------------------------------------------
__device__ __half g_Ah[3 * ME];   // split activations (fp16 hi): q,k,v
__device__ __half g_Al[3 * ME];   // split activations (fp16 lo)
__device__ __half g_Wh[4 * EE];   // weights fp16 single, transposed [N][K]: q,k,v,o
__device__ __half g_Ph[3 * ME];   // projected Q,K,V (fp16 single; Q pre-scaled)
__device__ __half g_Chi[ME];      // attention context (fp16 hi)
__device__ __half g_Clo[ME];      // attention context (fp16 lo)

// ---------------------------------------------------------------------------
// Helpers (legal on base sm_103 target)
// ---------------------------------------------------------------------------
__device__ __forceinline__ uint32_t smem_u32(const void* p) {
    uint32_t a;
    asm("{ .reg .u64 t; cvta.to.shared.u64 t, %1; cvt.u32.u64 %0, t; }"
        : "=r"(a) : "l"(p));
    return a;
}
__device__ __forceinline__ void ldsm_x4(uint32_t* r, uint32_t addr) {
    asm volatile("ldmatrix.sync.aligned.m8n8.x4.shared.b16 {%0,%1,%2,%3}, [%4];"
        : "=r"(r[0]), "=r"(r[1]), "=r"(r[2]), "=r"(r[3]) : "r"(addr));
}
__device__ __forceinline__ void ldsm_x2(uint32_t* r, uint32_t addr) {
    asm volatile("ldmatrix.sync.aligned.m8n8.x2.shared.b16 {%0,%1}, [%2];"
        : "=r"(r[0]), "=r"(r[1]) : "r"(addr));
}
__device__ __forceinline__ void ldsm_x4t(uint32_t* r, uint32_t addr) {
    asm volatile("ldmatrix.sync.aligned.m8n8.x4.trans.shared.b16 {%0,%1,%2,%3}, [%4];"
        : "=r"(r[0]), "=r"(r[1]), "=r"(r[2]), "=r"(r[3]) : "r"(addr));
}
__device__ __forceinline__ void mma16816h(float* c, const uint32_t* a, const uint32_t* b) {
    asm volatile(
        "mma.sync.aligned.m16n8k16.row.col.f32.f16.f16.f32 "
        "{%0,%1,%2,%3}, {%4,%5,%6,%7}, {%8,%9}, {%0,%1,%2,%3};"
        : "+f"(c[0]), "+f"(c[1]), "+f"(c[2]), "+f"(c[3])
        : "r"(a[0]), "r"(a[1]), "r"(a[2]), "r"(a[3]), "r"(b[0]), "r"(b[1]));
}
__device__ __forceinline__ float ex2f(float x) {
    float y; asm("ex2.approx.f32 %0, %1;" : "=f"(y) : "f"(x)); return y;
}
__device__ __forceinline__ uint32_t packhf(float a, float b) {
    uint32_t r; asm("cvt.rn.f16x2.f32 %0, %1, %2;" : "=r"(r) : "f"(b), "f"(a));
    return r;
}
__device__ __forceinline__ float lohf(uint32_t p) {
    return __half2float(__ushort_as_half((unsigned short)(p & 0xffffu)));
}
__device__ __forceinline__ float hihf(uint32_t p) {
    return __half2float(__ushort_as_half((unsigned short)(p >> 16)));
}
__device__ __forceinline__ void split4h(float4 v, uint2& hi, uint2& lo) {
    uint32_t h0 = packhf(v.x, v.y), h1 = packhf(v.z, v.w);
    hi.x = h0; hi.y = h1;
    lo.x = packhf(v.x - lohf(h0), v.y - hihf(h0));
    lo.y = packhf(v.z - lohf(h1), v.w - hihf(h1));
}

__device__ __forceinline__ void cpasync16(uint32_t saddr, const void* g) {
    asm volatile("cp.async.cg.shared.global [%0], [%1], 16;" :: "r"(saddr), "l"(g));
}
#define CP_COMMIT() asm volatile("cp.async.commit_group;" ::: "memory")
#define CP_WAIT1()  asm volatile("cp.async.wait_group 1;" ::: "memory")
#define CP_WAIT0()  asm volatile("cp.async.wait_group 0;" ::: "memory")

#define SMEM_SWIZZLE_128B(off) ((off) ^ (((off) >> 3) & 0x70))
#define SMEM_SWIZZLE_64B(off)  ((off) ^ (((off) >> 3) & 0x30))

// ---------------------------------------------------------------------------
// Batched conversions
// ---------------------------------------------------------------------------
__global__ void __launch_bounds__(256) splitA3_kernel(
    const float* __restrict__ x0, const float* __restrict__ x1,
    const float* __restrict__ x2,
    __half* __restrict__ hi, __half* __restrict__ lo)
{
    const int p = blockIdx.z;
    const float* x = (p == 0) ? x0 : (p == 1) ? x1 : x2;
    size_t i = (size_t)blockIdx.x * 256 + threadIdx.x;
    float4 v = ((const float4*)x)[i];
    uint2 h, l;
    split4h(v, h, l);
    ((uint2*)(hi + p * ME))[i] = h;
    ((uint2*)(lo + p * ME))[i] = l;
}

__global__ void __launch_bounds__(256) convW4_kernel(
    const float* __restrict__ W0, const float* __restrict__ W1,
    const float* __restrict__ W2, const float* __restrict__ W3,
    __half* __restrict__ whAll)
{
    __shared__ float t[32][33];
    const int p = blockIdx.z;
    const float* W = (p == 0) ? W0 : (p == 1) ? W1 : (p == 2) ? W2 : W3;
    __half* wh = whAll + p * EE;
    int tx = threadIdx.x & 31, ty = threadIdx.x >> 5;
    int nb = blockIdx.x * 32, kb = blockIdx.y * 32;
    #pragma unroll
    for (int i = 0; i < 4; ++i) {
        int k = kb + ty + i * 8;
        t[ty + i * 8][tx] = W[(size_t)k * E_ + nb + tx];
    }
    __syncthreads();
    #pragma unroll
    for (int i = 0; i < 4; ++i) {
        int n = nb + ty + i * 8;
        wh[(size_t)n * E_ + kb + tx] = __float2half(t[tx][ty + i * 8]);
    }
}

// ---------------------------------------------------------------------------
// 2-term fp16 GEMM core (validated R14): C = (Ah + Al) * Wh^T + bias
//   BK=32, 2-stage cp.async, 48KB smem.
// OUT: 0 = fp32 C, 1 = fp16 single (Ch, output scaled by oscale)
// ---------------------------------------------------------------------------
#define G_STAGE 24576
#define G_TILE  8192
#define GEMM_SMEM (2 * G_STAGE)
#define G_NKC 64   // K / 32

template <int OUT>
__device__ __forceinline__ void gemm_body(
    const __half* __restrict__ Ah, const __half* __restrict__ Al,
    const __half* __restrict__ Wh,
    const float* __restrict__ bias, float oscale, float* __restrict__ C,
    __half* __restrict__ Ch,
    char* smc, int bx, int by)
{
    const uint32_t sb = smem_u32(smc);
    const int tid  = threadIdx.x;
    const int wid  = tid >> 5;
    const int lane = tid & 31;

    const int warpM = (wid >> 2) * 64;
    const int warpN = (wid & 3) * 32;

    const size_t aRow0 = (size_t)by * 128;
    const size_t bRow0 = (size_t)bx * 128;

    float acc[4][4][4];
    #pragma unroll
    for (int mi = 0; mi < 4; ++mi)
        #pragma unroll
        for (int ni = 0; ni < 4; ++ni)
            #pragma unroll
            for (int j = 0; j < 4; ++j) acc[mi][ni][j] = 0.f;

    const uint32_t aRowL = warpM + (lane & 15);
    const uint32_t aColL = (lane >> 4) * 8;
    const uint32_t bRowL = warpN + (lane & 7);
    const uint32_t bColL = ((lane >> 3) & 1) * 8;

    const int ldR0 = tid >> 2;
    const int ldS  = tid & 3;

    auto load_stage = [&](int kc, int st) {
        const int k0 = kc * 32;
        const uint32_t base = sb + st * G_STAGE;
        #pragma unroll
        for (int it = 0; it < 2; ++it) {
            const int r = ldR0 + it * 64;
            const uint32_t o = SMEM_SWIZZLE_64B((uint32_t)(r * 64 + ldS * 16));
            const size_t gA = (aRow0 + r) * E_ + k0 + ldS * 8;
            const size_t gB = (bRow0 + r) * E_ + k0 + ldS * 8;
            cpasync16(base + o,              Ah + gA);
            cpasync16(base + G_TILE + o,     Al + gA);
            cpasync16(base + 2 * G_TILE + o, Wh + gB);
        }
    };

    load_stage(0, 0); CP_COMMIT();
    load_stage(1, 1); CP_COMMIT();

    for (int kc = 0; kc < G_NKC; ++kc) {
        if (kc == G_NKC - 1) { CP_WAIT0(); } else { CP_WAIT1(); }
        __syncthreads();

        const uint32_t SAH = sb + (kc & 1) * G_STAGE;
        const uint32_t SAL = SAH + G_TILE;
        const uint32_t SBH = SAH + 2 * G_TILE;

        #pragma unroll
        for (int ks = 0; ks < 2; ++ks) {
            const uint32_t kb = ks * 16;
            uint32_t ah[4][4], al[4][4], bh[4][2];
            #pragma unroll
            for (int mi = 0; mi < 4; ++mi) {
                uint32_t off = (aRowL + mi * 16) * 64 + (kb + aColL) * 2;
                off = SMEM_SWIZZLE_64B(off);
                ldsm_x4(ah[mi], SAH + off);
                ldsm_x4(al[mi], SAL + off);
            }
            #pragma unroll
            for (int ni = 0; ni < 4; ++ni) {
                uint32_t off = (bRowL + ni * 8) * 64 + (kb + bColL) * 2;
                off = SMEM_SWIZZLE_64B(off);
                ldsm_x2(bh[ni], SBH + off);
            }
            #pragma unroll
            for (int mi = 0; mi < 4; ++mi)
                #pragma unroll
                for (int ni = 0; ni < 4; ++ni) {
                    mma16816h(acc[mi][ni], ah[mi], bh[ni]);
                    mma16816h(acc[mi][ni], al[mi], bh[ni]);
                }
        }
        __syncthreads();
        if (kc + 2 < G_NKC) { load_stage(kc + 2, kc & 1); CP_COMMIT(); }
    }

    const int rQuad = lane >> 2;
    const int cPair = (lane & 3) * 2;
    #pragma unroll
    for (int mi = 0; mi < 4; ++mi) {
        #pragma unroll
        for (int ni = 0; ni < 4; ++ni) {
            int row = by * 128 + warpM + mi * 16 + rQuad;
            int col = bx * 128 + warpN + ni * 8 + cPair;
            float b0 = bias[col], b1 = bias[col + 1];
            float o00 = acc[mi][ni][0] + b0, o01 = acc[mi][ni][1] + b1;
            float o10 = acc[mi][ni][2] + b0, o11 = acc[mi][ni][3] + b1;
            if constexpr (OUT == 1) {
                o00 *= oscale; o01 *= oscale; o10 *= oscale; o11 *= oscale;
                size_t i0 = ((size_t)row * E_ + col) >> 1;
                size_t i1 = ((size_t)(row + 8) * E_ + col) >> 1;
                ((uint32_t*)Ch)[i0] = packhf(o00, o01);
                ((uint32_t*)Ch)[i1] = packhf(o10, o11);
            } else {
                *(float2*)(C + (size_t)row * E_ + col)       = make_float2(o00, o01);
                *(float2*)(C + (size_t)(row + 8) * E_ + col) = make_float2(o10, o11);
            }
        }
    }
}

// Batched projection GEMM: blockIdx.z = 0(Q, pre-scaled), 1(K), 2(V)
__global__ void __launch_bounds__(256, 2) gemm_proj3_kernel(
    const __half* __restrict__ AhAll, const __half* __restrict__ AlAll,
    const __half* __restrict__ WhAll,
    const float* __restrict__ b0, const float* __restrict__ b1,
    const float* __restrict__ b2,
    __half* __restrict__ PhAll)
{
    extern __shared__ char smc[];
    const int p = blockIdx.z;
    const float* bias = (p == 0) ? b0 : (p == 1) ? b1 : b2;
    const float oscale = (p == 0) ? QSCALE : 1.0f;
    gemm_body<1>(AhAll + p * ME, AlAll + p * ME, WhAll + p * EE,
                 bias, oscale, nullptr, PhAll + p * ME,
                 smc, blockIdx.x, blockIdx.y);
}

__global__ void __launch_bounds__(256, 2) gemm_out_kernel(
    const __half* __restrict__ Ah, const __half* __restrict__ Al,
    const __half* __restrict__ Wh,
    const float* __restrict__ bias, float* __restrict__ C)
{
    extern __shared__ char smc[];
    gemm_body<0>(Ah, Al, Wh, bias, 1.0f, C, nullptr,
                 smc, blockIdx.x, blockIdx.y);
}

// ---------------------------------------------------------------------------
// Flash attention, fp16 single-term, BM=64, BN=64, 128 threads.
// Q pre-scaled by SCALE*log2e => softmax in log2 domain (no scale muls).
// Smem: Q 16KB + 2 stages x (K,V [64][128] fp16 = 32KB) = 80KB -> 2 CTA/SM.
// ---------------------------------------------------------------------------
#define FQ     0        // subtiles @0, @8192
#define FKV0   16384
#define KV_STAGE 32768
#define KV_K   0        // subtiles @0, @8192
#define KV_V   16384    // subtiles @16384, @24576 (stage-relative)
#define FL_SMEM (16384 + 2 * 32768)   // 81920

__global__ void __launch_bounds__(128, 2) flash_mma_kernel(
    const __half* __restrict__ Qh, const __half* __restrict__ Kh,
    const __half* __restrict__ Vh,
    __half* __restrict__ Chi, __half* __restrict__ Clo)
{
    extern __shared__ char sm[];
    const uint32_t sb = smem_u32(sm);

    const int qt = blockIdx.x, h = blockIdx.y, b = blockIdx.z;
    const int tid = threadIdx.x, w = tid >> 5, lane = tid & 31;

    const size_t qrow0 = (size_t)b * S_ + qt * 64;
    const size_t hcol = (size_t)h * D_;

    // KV stage loader: K,V tiles [64][128] fp16, 2 subtiles of [64][64] each
    auto load_kv = [&](int kt, int st) {
        const size_t krow0 = (size_t)b * S_ + kt * 64;
        const uint32_t base = sb + FKV0 + st * KV_STAGE;
        #pragma unroll
        for (int it = 0; it < 8; ++it) {
            int idx = tid + it * 128;      // 0..1023 chunks of 16B
            int r = idx >> 4, s = idx & 15;
            uint32_t off = (uint32_t)(s >> 3) * 8192 +
                           SMEM_SWIZZLE_128B((uint32_t)(r * 128 + (s & 7) * 16));
            const size_t g = (krow0 + r) * E_ + hcol + s * 8;
            cpasync16(base + KV_K + off, Kh + g);
            cpasync16(base + KV_V + off, Vh + g);
        }
    };

    load_kv(0, 0); CP_COMMIT();
    load_kv(1, 1); CP_COMMIT();

    // Q fill: [64][128] fp16 (already scaled by SCALE*log2e)
    #pragma unroll
    for (int it = 0; it < 8; ++it) {
        int idx = tid + it * 128;
        int r = idx >> 4, s = idx & 15;
        uint32_t off = (uint32_t)(s >> 3) * 8192 +
                       SMEM_SWIZZLE_128B((uint32_t)(r * 128 + (s & 7) * 16));
        const size_t g = (qrow0 + r) * E_ + hcol + s * 8;
        *(uint4*)(sm + FQ + off) = *(const uint4*)(Qh + g);
    }

    float oacc[16][4];
    #pragma unroll
    for (int f = 0; f < 16; ++f)
        #pragma unroll
        for (int j = 0; j < 4; ++j) oacc[f][j] = 0.f;
    float m0 = -1e30f, m1 = -1e30f, l0 = 0.f, l1 = 0.f;

    const uint32_t aRowL = w * 16 + (lane & 15);
    const uint32_t aColL = (lane >> 4) * 8;
    const uint32_t bRowL = lane & 7;
    const uint32_t bColL = ((lane >> 3) & 1) * 8;
    const uint32_t vR = lane & 7, vM = lane >> 3;

    for (int kt = 0; kt < 32; ++kt) {
        if (kt == 31) { CP_WAIT0(); } else { CP_WAIT1(); }
        __syncthreads();
        const uint32_t kvb = sb + FKV0 + (kt & 1) * KV_STAGE;

        // ---- S(log2) = Qs K^T : 16x64 per warp ----
        float sacc[8][4];
        #pragma unroll
        for (int ni = 0; ni < 8; ++ni)
            #pragma unroll
            for (int j = 0; j < 4; ++j) sacc[ni][j] = 0.f;

        #pragma unroll
        for (int half = 0; half < 2; ++half) {
            #pragma unroll
            for (int ks = 0; ks < 4; ++ks) {
                const uint32_t kb = ks * 16;
                uint32_t ah[4];
                uint32_t aoff = SMEM_SWIZZLE_128B(aRowL * 128 + (kb + aColL) * 2);
                ldsm_x4(ah, sb + FQ + half * 8192 + aoff);
                #pragma unroll
                for (int ni = 0; ni < 8; ++ni) {
                    uint32_t bh[2];
                    uint32_t boff = SMEM_SWIZZLE_128B((bRowL + ni * 8) * 128 + (kb + bColL) * 2);
                    ldsm_x2(bh, kvb + KV_K + half * 8192 + boff);
                    mma16816h(sacc[ni], ah, bh);
                }
            }
        }

        // ---- online softmax (log2 domain) ----
        float mx0 = -1e30f, mx1 = -1e30f;
        #pragma unroll
        for (int ni = 0; ni < 8; ++ni) {
            mx0 = fmaxf(mx0, fmaxf(sacc[ni][0], sacc[ni][1]));
            mx1 = fmaxf(mx1, fmaxf(sacc[ni][2], sacc[ni][3]));
        }
        mx0 = fmaxf(mx0, __shfl_xor_sync(0xffffffffu, mx0, 1));
        mx0 = fmaxf(mx0, __shfl_xor_sync(0xffffffffu, mx0, 2));
        mx1 = fmaxf(mx1, __shfl_xor_sync(0xffffffffu, mx1, 1));
        mx1 = fmaxf(mx1, __shfl_xor_sync(0xffffffffu, mx1, 2));
        const float mn0 = fmaxf(m0, mx0), mn1 = fmaxf(m1, mx1);
        const float al0 = ex2f(m0 - mn0), al1 = ex2f(m1 - mn1);
        m0 = mn0; m1 = mn1;

        uint32_t ph[8][2];
        float ls0 = 0.f, ls1 = 0.f;
        #pragma unroll
        for (int ni = 0; ni < 8; ++ni) {
            float p00 = ex2f(sacc[ni][0] - mn0);
            float p01 = ex2f(sacc[ni][1] - mn0);
            float p10 = ex2f(sacc[ni][2] - mn1);
            float p11 = ex2f(sacc[ni][3] - mn1);
            ls0 += p00 + p01;
            ls1 += p10 + p11;
            ph[ni][0] = packhf(p00, p01);
            ph[ni][1] = packhf(p10, p11);
        }
        ls0 += __shfl_xor_sync(0xffffffffu, ls0, 1);
        ls0 += __shfl_xor_sync(0xffffffffu, ls0, 2);
        ls1 += __shfl_xor_sync(0xffffffffu, ls1, 1);
        ls1 += __shfl_xor_sync(0xffffffffu, ls1, 2);
        l0 = l0 * al0 + ls0;
        l1 = l1 * al1 + ls1;

        #pragma unroll
        for (int f = 0; f < 16; ++f) {
            oacc[f][0] *= al0; oacc[f][1] *= al0;
            oacc[f][2] *= al1; oacc[f][3] *= al1;
        }

        // ---- O += P V : P is 16x64 -> 4 k-fragments ----
        #pragma unroll
        for (int kf = 0; kf < 4; ++kf) {
            uint32_t aPh[4] = { ph[2*kf][0], ph[2*kf][1], ph[2*kf+1][0], ph[2*kf+1][1] };
            #pragma unroll
            for (int nd = 0; nd < 8; ++nd) {
                const uint32_t sub = (nd >> 2) * 8192;
                const uint32_t dd = (nd & 3) * 16;
                const uint32_t kvr = kf * 16 + (vM & 1) * 8 + vR;   // 0..63
                const uint32_t dc = dd + (vM >> 1) * 8;
                const uint32_t voff = SMEM_SWIZZLE_128B(kvr * 128 + dc * 2);
                uint32_t bh4[4];
                ldsm_x4t(bh4, kvb + KV_V + sub + voff);
                mma16816h(oacc[2*nd],     aPh, bh4);
                mma16816h(oacc[2*nd + 1], aPh, bh4 + 2);
            }
        }

        __syncthreads();
        if (kt + 2 < 32) { load_kv(kt + 2, kt & 1); CP_COMMIT(); }
    }

    // ---- finalize: fp16 split context (feeds out-GEMM) ----
    const float inv0 = 1.f / l0, inv1 = 1.f / l1;
    const int rQuad = lane >> 2, cPair = (lane & 3) * 2;
    const size_t row0 = qrow0 + w * 16 + rQuad;
    #pragma unroll
    for (int f = 0; f < 16; ++f) {
        int d = f * 8 + cPair;
        float o00 = oacc[f][0] * inv0, o01 = oacc[f][1] * inv0;
        float o10 = oacc[f][2] * inv1, o11 = oacc[f][3] * inv1;
        size_t i0 = (row0 * E_ + hcol + d) >> 1;
        size_t i1 = ((row0 + 8) * E_ + hcol + d) >> 1;
        uint32_t h0 = packhf(o00, o01);
        uint32_t h1 = packhf(o10, o11);
        ((uint32_t*)Chi)[i0] = h0;
        ((uint32_t*)Chi)[i1] = h1;
        ((uint32_t*)Clo)[i0] = packhf(o00 - lohf(h0), o01 - hihf(h0));
        ((uint32_t*)Clo)[i1] = packhf(o10 - lohf(h1), o11 - hihf(h1));
    }
}

// ---------------------------------------------------------------------------
extern "C" void kernel_launch(void* const* d_in, const int* in_sizes, int n_in,
                              void* d_out, int out_size)
{
    const float* query  = (const float*)d_in[0];
    const float* key_in = (const float*)d_in[1];
    const float* value  = (const float*)d_in[2];
    const float* Wq = (const float*)d_in[3];
    const float* bq = (const float*)d_in[4];
    const float* Wk = (const float*)d_in[5];
    const float* bk = (const float*)d_in[6];
    const float* Wv = (const float*)d_in[7];
    const float* bv = (const float*)d_in[8];
    const float* Wo = (const float*)d_in[9];
    const float* bo = (const float*)d_in[10];
    float* out = (float*)d_out;

    __half *Ah, *Al, *Wh, *Ph, *Chi, *Clo;
    cudaGetSymbolAddress((void**)&Ah,  g_Ah);
    cudaGetSymbolAddress((void**)&Al,  g_Al);
    cudaGetSymbolAddress((void**)&Wh,  g_Wh);
    cudaGetSymbolAddress((void**)&Ph,  g_Ph);
    cudaGetSymbolAddress((void**)&Chi, g_Chi);
    cudaGetSymbolAddress((void**)&Clo, g_Clo);

    cudaFuncSetAttribute(flash_mma_kernel,
                         cudaFuncAttributeMaxDynamicSharedMemorySize, FL_SMEM);
    cudaFuncSetAttribute(gemm_proj3_kernel,
                         cudaFuncAttributeMaxDynamicSharedMemorySize, GEMM_SMEM);
    cudaFuncSetAttribute(gemm_out_kernel,
                         cudaFuncAttributeMaxDynamicSharedMemorySize, GEMM_SMEM);

    const dim3 cw(E_ / 32, E_ / 32, 4);
    const dim3 sa((MROWS * E_ / 4) / 256, 1, 3);
    const dim3 g3(E_ / 128, MROWS / 128, 3);
    const dim3 gg(E_ / 128, MROWS / 128);
    const dim3 fg(S_ / 64, H_, B_);

    convW4_kernel<<<cw, 256>>>(Wq, Wk, Wv, Wo, Wh);
    splitA3_kernel<<<sa, 256>>>(query, key_in, value, Ah, Al);

    // Q,K,V projections (2-term fp16) -> fp16 outputs (Q pre-scaled)
    gemm_proj3_kernel<<<g3, 256, GEMM_SMEM>>>(Ah, Al, Wh, bq, bk, bv, Ph);

    // Attention (fp16 single-term, log2-domain softmax) -> fp16 split context
    flash_mma_kernel<<<fg, 128, FL_SMEM>>>(
        Ph + 0 * ME, Ph + 1 * ME, Ph + 2 * ME, Chi, Clo);

    // Output projection (2-term fp16) -> fp32 out
    gemm_out_kernel<<<gg, 256, GEMM_SMEM>>>(Chi, Clo, Wh + 3 * EE, bo, out);
}

// round 16
// speedup vs baseline: 1.2442x; 1.2442x over previous
#include <cuda_runtime.h>
#include <cuda_bf16.h>
#include <cuda_fp16.h>
#include <cstdint>

// Problem constants
#define B_ 2
#define S_ 2048
#define E_ 2048
#define H_ 16
#define D_ 128
#define MROWS (B_ * S_)   // 4096
#define ME ((size_t)MROWS * E_)
#define EE ((size_t)E_ * E_)

// 1/sqrt(128) * log2(e)  — folded into Q projection output
#define QSCALE 0.12752262159188963f

// ---------------------------------------------------------------------------
// Scratch (no cudaMalloc allowed) — fp16 everywhere
// ---------------------------------------------------------------------------
__device__ __half g_Ah[3 * ME];   // split activations (fp16 hi): q,k,v
__device__ __half g_Al[3 * ME];   // split activations (fp16 lo)
__device__ __half g_Wh[4 * EE];   // weights fp16 single, transposed [N][K]: q,k,v,o
__device__ __half g_Ph[3 * ME];   // projected Q,K,V (fp16 single; Q pre-scaled)
__device__ __half g_Chi[ME];      // attention context (fp16 hi)
__device__ __half g_Clo[ME];      // attention context (fp16 lo)

// ---------------------------------------------------------------------------
// Helpers (legal on base sm_103 target)
// ---------------------------------------------------------------------------
__device__ __forceinline__ uint32_t smem_u32(const void* p) {
    uint32_t a;
    asm("{ .reg .u64 t; cvta.to.shared.u64 t, %1; cvt.u32.u64 %0, t; }"
        : "=r"(a) : "l"(p));
    return a;
}
__device__ __forceinline__ void ldsm_x4(uint32_t* r, uint32_t addr) {
    asm volatile("ldmatrix.sync.aligned.m8n8.x4.shared.b16 {%0,%1,%2,%3}, [%4];"
        : "=r"(r[0]), "=r"(r[1]), "=r"(r[2]), "=r"(r[3]) : "r"(addr));
}
__device__ __forceinline__ void ldsm_x2(uint32_t* r, uint32_t addr) {
    asm volatile("ldmatrix.sync.aligned.m8n8.x2.shared.b16 {%0,%1}, [%2];"
        : "=r"(r[0]), "=r"(r[1]) : "r"(addr));
}
__device__ __forceinline__ void ldsm_x4t(uint32_t* r, uint32_t addr) {
    asm volatile("ldmatrix.sync.aligned.m8n8.x4.trans.shared.b16 {%0,%1,%2,%3}, [%4];"
        : "=r"(r[0]), "=r"(r[1]), "=r"(r[2]), "=r"(r[3]) : "r"(addr));
}
__device__ __forceinline__ void mma16816h(float* c, const uint32_t* a, const uint32_t* b) {
    asm volatile(
        "mma.sync.aligned.m16n8k16.row.col.f32.f16.f16.f32 "
        "{%0,%1,%2,%3}, {%4,%5,%6,%7}, {%8,%9}, {%0,%1,%2,%3};"
        : "+f"(c[0]), "+f"(c[1]), "+f"(c[2]), "+f"(c[3])
        : "r"(a[0]), "r"(a[1]), "r"(a[2]), "r"(a[3]), "r"(b[0]), "r"(b[1]));
}
__device__ __forceinline__ float ex2f(float x) {
    float y; asm("ex2.approx.f32 %0, %1;" : "=f"(y) : "f"(x)); return y;
}
__device__ __forceinline__ uint32_t packhf(float a, float b) {
    uint32_t r; asm("cvt.rn.f16x2.f32 %0, %1, %2;" : "=r"(r) : "f"(b), "f"(a));
    return r;
}
__device__ __forceinline__ float lohf(uint32_t p) {
    return __half2float(__ushort_as_half((unsigned short)(p & 0xffffu)));
}
__device__ __forceinline__ float hihf(uint32_t p) {
    return __half2float(__ushort_as_half((unsigned short)(p >> 16)));
}
__device__ __forceinline__ void split4h(float4 v, uint2& hi, uint2& lo) {
    uint32_t h0 = packhf(v.x, v.y), h1 = packhf(v.z, v.w);
    hi.x = h0; hi.y = h1;
    lo.x = packhf(v.x - lohf(h0), v.y - hihf(h0));
    lo.y = packhf(v.z - lohf(h1), v.w - hihf(h1));
}

__device__ __forceinline__ void cpasync16(uint32_t saddr, const void* g) {
    asm volatile("cp.async.cg.shared.global [%0], [%1], 16;" :: "r"(saddr), "l"(g));
}
#define CP_COMMIT() asm volatile("cp.async.commit_group;" ::: "memory")
#define CP_WAIT1()  asm volatile("cp.async.wait_group 1;" ::: "memory")
#define CP_WAIT0()  asm volatile("cp.async.wait_group 0;" ::: "memory")

#define SMEM_SWIZZLE_128B(off) ((off) ^ (((off) >> 3) & 0x70))
#define SMEM_SWIZZLE_64B(off)  ((off) ^ (((off) >> 3) & 0x30))

// ---------------------------------------------------------------------------
// Batched conversions
// ---------------------------------------------------------------------------
__global__ void __launch_bounds__(256) splitA3_kernel(
    const float* __restrict__ x0, const float* __restrict__ x1,
    const float* __restrict__ x2,
    __half* __restrict__ hi, __half* __restrict__ lo)
{
    const int p = blockIdx.z;
    const float* x = (p == 0) ? x0 : (p == 1) ? x1 : x2;
    size_t i = (size_t)blockIdx.x * 256 + threadIdx.x;
    float4 v = ((const float4*)x)[i];
    uint2 h, l;
    split4h(v, h, l);
    ((uint2*)(hi + p * ME))[i] = h;
    ((uint2*)(lo + p * ME))[i] = l;
}

__global__ void __launch_bounds__(256) convW4_kernel(
    const float* __restrict__ W0, const float* __restrict__ W1,
    const float* __restrict__ W2, const float* __restrict__ W3,
    __half* __restrict__ whAll)
{
    __shared__ float t[32][33];
    const int p = blockIdx.z;
    const float* W = (p == 0) ? W0 : (p == 1) ? W1 : (p == 2) ? W2 : W3;
    __half* wh = whAll + p * EE;
    int tx = threadIdx.x & 31, ty = threadIdx.x >> 5;
    int nb = blockIdx.x * 32, kb = blockIdx.y * 32;
    #pragma unroll
    for (int i = 0; i < 4; ++i) {
        int k = kb + ty + i * 8;
        t[ty + i * 8][tx] = W[(size_t)k * E_ + nb + tx];
    }
    __syncthreads();
    #pragma unroll
    for (int i = 0; i < 4; ++i) {
        int n = nb + ty + i * 8;
        wh[(size_t)n * E_ + kb + tx] = __float2half(t[tx][ty + i * 8]);
    }
}

// ---------------------------------------------------------------------------
// fp16 GEMM core: C = (Ah [+ Al]) * Wh^T + bias
//   BK=32, 2-stage cp.async. TERMS=2: stage 24KB; TERMS=1: stage 16KB.
// OUT: 0 = fp32 C, 1 = fp16 single (Ch, output scaled by oscale)
// ---------------------------------------------------------------------------
#define G_TILE  8192
#define GEMM_SMEM (2 * 24576)   // max stage config
#define G_NKC 64   // K / 32

template <int OUT, int TERMS>
__device__ __forceinline__ void gemm_body(
    const __half* __restrict__ Ah, const __half* __restrict__ Al,
    const __half* __restrict__ Wh,
    const float* __restrict__ bias, float oscale, float* __restrict__ C,
    __half* __restrict__ Ch,
    char* smc, int bx, int by)
{
    constexpr uint32_t STAGE = (TERMS == 2) ? 24576u : 16384u;
    constexpr uint32_t WOFF  = (TERMS == 2) ? 16384u : 8192u;

    const uint32_t sb = smem_u32(smc);
    const int tid  = threadIdx.x;
    const int wid  = tid >> 5;
    const int lane = tid & 31;

    const int warpM = (wid >> 2) * 64;
    const int warpN = (wid & 3) * 32;

    const size_t aRow0 = (size_t)by * 128;
    const size_t bRow0 = (size_t)bx * 128;

    float acc[4][4][4];
    #pragma unroll
    for (int mi = 0; mi < 4; ++mi)
        #pragma unroll
        for (int ni = 0; ni < 4; ++ni)
            #pragma unroll
            for (int j = 0; j < 4; ++j) acc[mi][ni][j] = 0.f;

    const uint32_t aRowL = warpM + (lane & 15);
    const uint32_t aColL = (lane >> 4) * 8;
    const uint32_t bRowL = warpN + (lane & 7);
    const uint32_t bColL = ((lane >> 3) & 1) * 8;

    const int ldR0 = tid >> 2;
    const int ldS  = tid & 3;

    auto load_stage = [&](int kc, int st) {
        const int k0 = kc * 32;
        const uint32_t base = sb + st * STAGE;
        #pragma unroll
        for (int it = 0; it < 2; ++it) {
            const int r = ldR0 + it * 64;
            const uint32_t o = SMEM_SWIZZLE_64B((uint32_t)(r * 64 + ldS * 16));
            const size_t gA = (aRow0 + r) * E_ + k0 + ldS * 8;
            const size_t gB = (bRow0 + r) * E_ + k0 + ldS * 8;
            cpasync16(base + o, Ah + gA);
            if constexpr (TERMS == 2) cpasync16(base + G_TILE + o, Al + gA);
            cpasync16(base + WOFF + o, Wh + gB);
        }
    };

    load_stage(0, 0); CP_COMMIT();
    load_stage(1, 1); CP_COMMIT();

    for (int kc = 0; kc < G_NKC; ++kc) {
        if (kc == G_NKC - 1) { CP_WAIT0(); } else { CP_WAIT1(); }
        __syncthreads();

        const uint32_t SAH = sb + (kc & 1) * STAGE;
        const uint32_t SAL = SAH + G_TILE;
        const uint32_t SBH = SAH + WOFF;

        #pragma unroll
        for (int ks = 0; ks < 2; ++ks) {
            const uint32_t kb = ks * 16;
            uint32_t ah[4][4], al[4][4], bh[4][2];
            #pragma unroll
            for (int mi = 0; mi < 4; ++mi) {
                uint32_t off = (aRowL + mi * 16) * 64 + (kb + aColL) * 2;
                off = SMEM_SWIZZLE_64B(off);
                ldsm_x4(ah[mi], SAH + off);
                if constexpr (TERMS == 2) ldsm_x4(al[mi], SAL + off);
            }
            #pragma unroll
            for (int ni = 0; ni < 4; ++ni) {
                uint32_t off = (bRowL + ni * 8) * 64 + (kb + bColL) * 2;
                off = SMEM_SWIZZLE_64B(off);
                ldsm_x2(bh[ni], SBH + off);
            }
            #pragma unroll
            for (int mi = 0; mi < 4; ++mi)
                #pragma unroll
                for (int ni = 0; ni < 4; ++ni) {
                    mma16816h(acc[mi][ni], ah[mi], bh[ni]);
                    if constexpr (TERMS == 2)
                        mma16816h(acc[mi][ni], al[mi], bh[ni]);
                }
        }
        __syncthreads();
        if (kc + 2 < G_NKC) { load_stage(kc + 2, kc & 1); CP_COMMIT(); }
    }

    const int rQuad = lane >> 2;
    const int cPair = (lane & 3) * 2;
    #pragma unroll
    for (int mi = 0; mi < 4; ++mi) {
        #pragma unroll
        for (int ni = 0; ni < 4; ++ni) {
            int row = by * 128 + warpM + mi * 16 + rQuad;
            int col = bx * 128 + warpN + ni * 8 + cPair;
            float b0 = bias[col], b1 = bias[col + 1];
            float o00 = acc[mi][ni][0] + b0, o01 = acc[mi][ni][1] + b1;
            float o10 = acc[mi][ni][2] + b0, o11 = acc[mi][ni][3] + b1;
            if constexpr (OUT == 1) {
                o00 *= oscale; o01 *= oscale; o10 *= oscale; o11 *= oscale;
                size_t i0 = ((size_t)row * E_ + col) >> 1;
                size_t i1 = ((size_t)(row + 8) * E_ + col) >> 1;
                ((uint32_t*)Ch)[i0] = packhf(o00, o01);
                ((uint32_t*)Ch)[i1] = packhf(o10, o11);
            } else {
                *(float2*)(C + (size_t)row * E_ + col)       = make_float2(o00, o01);
                *(float2*)(C + (size_t)(row + 8) * E_ + col) = make_float2(o10, o11);
            }
        }
    }
}

// Batched projection GEMM: z=0 Q (2-term, pre-scaled), z=1 K (1-term), z=2 V (1-term)
__global__ void __launch_bounds__(256, 2) gemm_proj3_kernel(
    const __half* __restrict__ AhAll, const __half* __restrict__ AlAll,
    const __half* __restrict__ WhAll,
    const float* __restrict__ b0, const float* __restrict__ b1,
    const float* __restrict__ b2,
    __half* __restrict__ PhAll)
{
    extern __shared__ char smc[];
    const int p = blockIdx.z;
    if (p == 0) {
        gemm_body<1, 2>(AhAll, AlAll, WhAll, b0, QSCALE, nullptr, PhAll,
                        smc, blockIdx.x, blockIdx.y);
    } else if (p == 1) {
        gemm_body<1, 1>(AhAll + ME, nullptr, WhAll + EE, b1, 1.0f, nullptr,
                        PhAll + ME, smc, blockIdx.x, blockIdx.y);
    } else {
        gemm_body<1, 1>(AhAll + 2 * ME, nullptr, WhAll + 2 * EE, b2, 1.0f, nullptr,
                        PhAll + 2 * ME, smc, blockIdx.x, blockIdx.y);
    }
}

__global__ void __launch_bounds__(256, 2) gemm_out_kernel(
    const __half* __restrict__ Ah, const __half* __restrict__ Al,
    const __half* __restrict__ Wh,
    const float* __restrict__ bias, float* __restrict__ C)
{
    extern __shared__ char smc[];
    gemm_body<0, 2>(Ah, Al, Wh, bias, 1.0f, C, nullptr,
                    smc, blockIdx.x, blockIdx.y);
}

// ---------------------------------------------------------------------------
// Flash attention (R15, validated): fp16 single-term, BM=64, BN=64,
// 128 threads, log2-domain softmax, 80KB smem -> 2 CTA/SM.
// ---------------------------------------------------------------------------
#define FQ     0        // subtiles @0, @8192
#define FKV0   16384
#define KV_STAGE 32768
#define KV_K   0        // subtiles @0, @8192
#define KV_V   16384    // subtiles @16384, @24576 (stage-relative)
#define FL_SMEM (16384 + 2 * 32768)   // 81920

__global__ void __launch_bounds__(128, 2) flash_mma_kernel(
    const __half* __restrict__ Qh, const __half* __restrict__ Kh,
    const __half* __restrict__ Vh,
    __half* __restrict__ Chi, __half* __restrict__ Clo)
{
    extern __shared__ char sm[];
    const uint32_t sb = smem_u32(sm);

    const int qt = blockIdx.x, h = blockIdx.y, b = blockIdx.z;
    const int tid = threadIdx.x, w = tid >> 5, lane = tid & 31;

    const size_t qrow0 = (size_t)b * S_ + qt * 64;
    const size_t hcol = (size_t)h * D_;

    auto load_kv = [&](int kt, int st) {
        const size_t krow0 = (size_t)b * S_ + kt * 64;
        const uint32_t base = sb + FKV0 + st * KV_STAGE;
        #pragma unroll
        for (int it = 0; it < 8; ++it) {
            int idx = tid + it * 128;      // 0..1023 chunks of 16B
            int r = idx >> 4, s = idx & 15;
            uint32_t off = (uint32_t)(s >> 3) * 8192 +
                           SMEM_SWIZZLE_128B((uint32_t)(r * 128 + (s & 7) * 16));
            const size_t g = (krow0 + r) * E_ + hcol + s * 8;
            cpasync16(base + KV_K + off, Kh + g);
            cpasync16(base + KV_V + off, Vh + g);
        }
    };

    load_kv(0, 0); CP_COMMIT();
    load_kv(1, 1); CP_COMMIT();

    #pragma unroll
    for (int it = 0; it < 8; ++it) {
        int idx = tid + it * 128;
        int r = idx >> 4, s = idx & 15;
        uint32_t off = (uint32_t)(s >> 3) * 8192 +
                       SMEM_SWIZZLE_128B((uint32_t)(r * 128 + (s & 7) * 16));
        const size_t g = (qrow0 + r) * E_ + hcol + s * 8;
        *(uint4*)(sm + FQ + off) = *(const uint4*)(Qh + g);
    }

    float oacc[16][4];
    #pragma unroll
    for (int f = 0; f < 16; ++f)
        #pragma unroll
        for (int j = 0; j < 4; ++j) oacc[f][j] = 0.f;
    float m0 = -1e30f, m1 = -1e30f, l0 = 0.f, l1 = 0.f;

    const uint32_t aRowL = w * 16 + (lane & 15);
    const uint32_t aColL = (lane >> 4) * 8;
    const uint32_t bRowL = lane & 7;
    const uint32_t bColL = ((lane >> 3) & 1) * 8;
    const uint32_t vR = lane & 7, vM = lane >> 3;

    for (int kt = 0; kt < 32; ++kt) {
        if (kt == 31) { CP_WAIT0(); } else { CP_WAIT1(); }
        __syncthreads();
        const uint32_t kvb = sb + FKV0 + (kt & 1) * KV_STAGE;

        float sacc[8][4];
        #pragma unroll
        for (int ni = 0; ni < 8; ++ni)
            #pragma unroll
            for (int j = 0; j < 4; ++j) sacc[ni][j] = 0.f;

        #pragma unroll
        for (int half = 0; half < 2; ++half) {
            #pragma unroll
            for (int ks = 0; ks < 4; ++ks) {
                const uint32_t kb = ks * 16;
                uint32_t ah[4];
                uint32_t aoff = SMEM_SWIZZLE_128B(aRowL * 128 + (kb + aColL) * 2);
                ldsm_x4(ah, sb + FQ + half * 8192 + aoff);
                #pragma unroll
                for (int ni = 0; ni < 8; ++ni) {
                    uint32_t bh[2];
                    uint32_t boff = SMEM_SWIZZLE_128B((bRowL + ni * 8) * 128 + (kb + bColL) * 2);
                    ldsm_x2(bh, kvb + KV_K + half * 8192 + boff);
                    mma16816h(sacc[ni], ah, bh);
                }
            }
        }

        float mx0 = -1e30f, mx1 = -1e30f;
        #pragma unroll
        for (int ni = 0; ni < 8; ++ni) {
            mx0 = fmaxf(mx0, fmaxf(sacc[ni][0], sacc[ni][1]));
            mx1 = fmaxf(mx1, fmaxf(sacc[ni][2], sacc[ni][3]));
        }
        mx0 = fmaxf(mx0, __shfl_xor_sync(0xffffffffu, mx0, 1));
        mx0 = fmaxf(mx0, __shfl_xor_sync(0xffffffffu, mx0, 2));
        mx1 = fmaxf(mx1, __shfl_xor_sync(0xffffffffu, mx1, 1));
        mx1 = fmaxf(mx1, __shfl_xor_sync(0xffffffffu, mx1, 2));
        const float mn0 = fmaxf(m0, mx0), mn1 = fmaxf(m1, mx1);
        const float al0 = ex2f(m0 - mn0), al1 = ex2f(m1 - mn1);
        m0 = mn0; m1 = mn1;

        uint32_t ph[8][2];
        float ls0 = 0.f, ls1 = 0.f;
        #pragma unroll
        for (int ni = 0; ni < 8; ++ni) {
            float p00 = ex2f(sacc[ni][0] - mn0);
            float p01 = ex2f(sacc[ni][1] - mn0);
            float p10 = ex2f(sacc[ni][2] - mn1);
            float p11 = ex2f(sacc[ni][3] - mn1);
            ls0 += p00 + p01;
            ls1 += p10 + p11;
            ph[ni][0] = packhf(p00, p01);
            ph[ni][1] = packhf(p10, p11);
        }
        ls0 += __shfl_xor_sync(0xffffffffu, ls0, 1);
        ls0 += __shfl_xor_sync(0xffffffffu, ls0, 2);
        ls1 += __shfl_xor_sync(0xffffffffu, ls1, 1);
        ls1 += __shfl_xor_sync(0xffffffffu, ls1, 2);
        l0 = l0 * al0 + ls0;
        l1 = l1 * al1 + ls1;

        #pragma unroll
        for (int f = 0; f < 16; ++f) {
            oacc[f][0] *= al0; oacc[f][1] *= al0;
            oacc[f][2] *= al1; oacc[f][3] *= al1;
        }

        #pragma unroll
        for (int kf = 0; kf < 4; ++kf) {
            uint32_t aPh[4] = { ph[2*kf][0], ph[2*kf][1], ph[2*kf+1][0], ph[2*kf+1][1] };
            #pragma unroll
            for (int nd = 0; nd < 8; ++nd) {
                const uint32_t sub = (nd >> 2) * 8192;
                const uint32_t dd = (nd & 3) * 16;
                const uint32_t kvr = kf * 16 + (vM & 1) * 8 + vR;   // 0..63
                const uint32_t dc = dd + (vM >> 1) * 8;
                const uint32_t voff = SMEM_SWIZZLE_128B(kvr * 128 + dc * 2);
                uint32_t bh4[4];
                ldsm_x4t(bh4, kvb + KV_V + sub + voff);
                mma16816h(oacc[2*nd],     aPh, bh4);
                mma16816h(oacc[2*nd + 1], aPh, bh4 + 2);
            }
        }

        __syncthreads();
        if (kt + 2 < 32) { load_kv(kt + 2, kt & 1); CP_COMMIT(); }
    }

    const float inv0 = 1.f / l0, inv1 = 1.f / l1;
    const int rQuad = lane >> 2, cPair = (lane & 3) * 2;
    const size_t row0 = qrow0 + w * 16 + rQuad;
    #pragma unroll
    for (int f = 0; f < 16; ++f) {
        int d = f * 8 + cPair;
        float o00 = oacc[f][0] * inv0, o01 = oacc[f][1] * inv0;
        float o10 = oacc[f][2] * inv1, o11 = oacc[f][3] * inv1;
        size_t i0 = (row0 * E_ + hcol + d) >> 1;
        size_t i1 = ((row0 + 8) * E_ + hcol + d) >> 1;
        uint32_t h0 = packhf(o00, o01);
        uint32_t h1 = packhf(o10, o11);
        ((uint32_t*)Chi)[i0] = h0;
        ((uint32_t*)Chi)[i1] = h1;
        ((uint32_t*)Clo)[i0] = packhf(o00 - lohf(h0), o01 - hihf(h0));
        ((uint32_t*)Clo)[i1] = packhf(o10 - lohf(h1), o11 - hihf(h1));
    }
}

// ---------------------------------------------------------------------------
extern "C" void kernel_launch(void* const* d_in, const int* in_sizes, int n_in,
                              void* d_out, int out_size)
{
    const float* query  = (const float*)d_in[0];
    const float* key_in = (const float*)d_in[1];
    const float* value  = (const float*)d_in[2];
    const float* Wq = (const float*)d_in[3];
    const float* bq = (const float*)d_in[4];
    const float* Wk = (const float*)d_in[5];
    const float* bk = (const float*)d_in[6];
    const float* Wv = (const float*)d_in[7];
    const float* bv = (const float*)d_in[8];
    const float* Wo = (const float*)d_in[9];
    const float* bo = (const float*)d_in[10];
    float* out = (float*)d_out;

    __half *Ah, *Al, *Wh, *Ph, *Chi, *Clo;
    cudaGetSymbolAddress((void**)&Ah,  g_Ah);
    cudaGetSymbolAddress((void**)&Al,  g_Al);
    cudaGetSymbolAddress((void**)&Wh,  g_Wh);
    cudaGetSymbolAddress((void**)&Ph,  g_Ph);
    cudaGetSymbolAddress((void**)&Chi, g_Chi);
    cudaGetSymbolAddress((void**)&Clo, g_Clo);

    cudaFuncSetAttribute(flash_mma_kernel,
                         cudaFuncAttributeMaxDynamicSharedMemorySize, FL_SMEM);
    cudaFuncSetAttribute(gemm_proj3_kernel,
                         cudaFuncAttributeMaxDynamicSharedMemorySize, GEMM_SMEM);
    cudaFuncSetAttribute(gemm_out_kernel,
                         cudaFuncAttributeMaxDynamicSharedMemorySize, GEMM_SMEM);

    const dim3 cw(E_ / 32, E_ / 32, 4);
    const dim3 sa((MROWS * E_ / 4) / 256, 1, 3);
    const dim3 g3(E_ / 128, MROWS / 128, 3);
    const dim3 gg(E_ / 128, MROWS / 128);
    const dim3 fg(S_ / 64, H_, B_);

    convW4_kernel<<<cw, 256>>>(Wq, Wk, Wv, Wo, Wh);
    splitA3_kernel<<<sa, 256>>>(query, key_in, value, Ah, Al);

    // Q (2-term, pre-scaled), K, V (1-term) projections in one launch
    gemm_proj3_kernel<<<g3, 256, GEMM_SMEM>>>(Ah, Al, Wh, bq, bk, bv, Ph);

    // Attention (fp16 single-term, log2-domain softmax) -> fp16 split context
    flash_mma_kernel<<<fg, 128, FL_SMEM>>>(
        Ph + 0 * ME, Ph + 1 * ME, Ph + 2 * ME, Chi, Clo);

    // Output projection (2-term fp16) -> fp32 out
    gemm_out_kernel<<<gg, 256, GEMM_SMEM>>>(Chi, Clo, Wh + 3 * EE, bo, out);
}

// round 17
// speedup vs baseline: 1.2675x; 1.0188x over previous
#include <cuda_runtime.h>
#include <cuda_bf16.h>
#include <cuda_fp16.h>
#include <cstdint>

// Problem constants
#define B_ 2
#define S_ 2048
#define E_ 2048
#define H_ 16
#define D_ 128
#define MROWS (B_ * S_)   // 4096
#define ME ((size_t)MROWS * E_)
#define EE ((size_t)E_ * E_)

// 1/sqrt(128) * log2(e)  — folded into Q projection output
#define QSCALE 0.12752262159188963f

// ---------------------------------------------------------------------------
// Scratch (no cudaMalloc allowed) — fp16 everywhere
// ---------------------------------------------------------------------------
__device__ __half g_Ah[3 * ME];   // split activations (fp16 hi): q,k,v
__device__ __half g_Al[ME];       // activation lo (query only — K/V are 1-term)
__device__ __half g_Wh[4 * EE];   // weights fp16 single, transposed [N][K]: q,k,v,o
__device__ __half g_Ph[3 * ME];   // projected Q,K,V (fp16 single; Q pre-scaled)
__device__ __half g_Chi[ME];      // attention context (fp16 hi)
__device__ __half g_Clo[ME];      // attention context (fp16 lo)

// ---------------------------------------------------------------------------
// Helpers (legal on base sm_103 target)
// ---------------------------------------------------------------------------
__device__ __forceinline__ uint32_t smem_u32(const void* p) {
    uint32_t a;
    asm("{ .reg .u64 t; cvta.to.shared.u64 t, %1; cvt.u32.u64 %0, t; }"
        : "=r"(a) : "l"(p));
    return a;
}
__device__ __forceinline__ void ldsm_x4(uint32_t* r, uint32_t addr) {
    asm volatile("ldmatrix.sync.aligned.m8n8.x4.shared.b16 {%0,%1,%2,%3}, [%4];"
        : "=r"(r[0]), "=r"(r[1]), "=r"(r[2]), "=r"(r[3]) : "r"(addr));
}
__device__ __forceinline__ void ldsm_x2(uint32_t* r, uint32_t addr) {
    asm volatile("ldmatrix.sync.aligned.m8n8.x2.shared.b16 {%0,%1}, [%2];"
        : "=r"(r[0]), "=r"(r[1]) : "r"(addr));
}
__device__ __forceinline__ void ldsm_x4t(uint32_t* r, uint32_t addr) {
    asm volatile("ldmatrix.sync.aligned.m8n8.x4.trans.shared.b16 {%0,%1,%2,%3}, [%4];"
        : "=r"(r[0]), "=r"(r[1]), "=r"(r[2]), "=r"(r[3]) : "r"(addr));
}
__device__ __forceinline__ void mma16816h(float* c, const uint32_t* a, const uint32_t* b) {
    asm volatile(
        "mma.sync.aligned.m16n8k16.row.col.f32.f16.f16.f32 "
        "{%0,%1,%2,%3}, {%4,%5,%6,%7}, {%8,%9}, {%0,%1,%2,%3};"
        : "+f"(c[0]), "+f"(c[1]), "+f"(c[2]), "+f"(c[3])
        : "r"(a[0]), "r"(a[1]), "r"(a[2]), "r"(a[3]), "r"(b[0]), "r"(b[1]));
}
__device__ __forceinline__ float ex2f(float x) {
    float y; asm("ex2.approx.f32 %0, %1;" : "=f"(y) : "f"(x)); return y;
}
__device__ __forceinline__ uint32_t packhf(float a, float b) {
    uint32_t r; asm("cvt.rn.f16x2.f32 %0, %1, %2;" : "=r"(r) : "f"(b), "f"(a));
    return r;
}
__device__ __forceinline__ float lohf(uint32_t p) {
    return __half2float(__ushort_as_half((unsigned short)(p & 0xffffu)));
}
__device__ __forceinline__ float hihf(uint32_t p) {
    return __half2float(__ushort_as_half((unsigned short)(p >> 16)));
}
__device__ __forceinline__ void split4h(float4 v, uint2& hi, uint2& lo) {
    uint32_t h0 = packhf(v.x, v.y), h1 = packhf(v.z, v.w);
    hi.x = h0; hi.y = h1;
    lo.x = packhf(v.x - lohf(h0), v.y - hihf(h0));
    lo.y = packhf(v.z - lohf(h1), v.w - hihf(h1));
}

__device__ __forceinline__ void cpasync16(uint32_t saddr, const void* g) {
    asm volatile("cp.async.cg.shared.global [%0], [%1], 16;" :: "r"(saddr), "l"(g));
}
#define CP_COMMIT() asm volatile("cp.async.commit_group;" ::: "memory")
#define CP_WAIT1()  asm volatile("cp.async.wait_group 1;" ::: "memory")
#define CP_WAIT0()  asm volatile("cp.async.wait_group 0;" ::: "memory")

#define SMEM_SWIZZLE_128B(off) ((off) ^ (((off) >> 3) & 0x70))
#define SMEM_SWIZZLE_64B(off)  ((off) ^ (((off) >> 3) & 0x30))

// ---------------------------------------------------------------------------
// Batched conversions
// ---------------------------------------------------------------------------
__global__ void __launch_bounds__(256) splitA3_kernel(
    const float* __restrict__ x0, const float* __restrict__ x1,
    const float* __restrict__ x2,
    __half* __restrict__ hi, __half* __restrict__ lo)
{
    const int p = blockIdx.z;
    const float* x = (p == 0) ? x0 : (p == 1) ? x1 : x2;
    size_t i = (size_t)blockIdx.x * 256 + threadIdx.x;
    float4 v = ((const float4*)x)[i];
    uint2 h, l;
    split4h(v, h, l);
    ((uint2*)(hi + p * ME))[i] = h;
    if (p == 0) ((uint2*)lo)[i] = l;   // lo needed only for Q (2-term)
}

__global__ void __launch_bounds__(256) convW4_kernel(
    const float* __restrict__ W0, const float* __restrict__ W1,
    const float* __restrict__ W2, const float* __restrict__ W3,
    __half* __restrict__ whAll)
{
    __shared__ float t[32][33];
    const int p = blockIdx.z;
    const float* W = (p == 0) ? W0 : (p == 1) ? W1 : (p == 2) ? W2 : W3;
    __half* wh = whAll + p * EE;
    int tx = threadIdx.x & 31, ty = threadIdx.x >> 5;
    int nb = blockIdx.x * 32, kb = blockIdx.y * 32;
    #pragma unroll
    for (int i = 0; i < 4; ++i) {
        int k = kb + ty + i * 8;
        t[ty + i * 8][tx] = W[(size_t)k * E_ + nb + tx];
    }
    __syncthreads();
    #pragma unroll
    for (int i = 0; i < 4; ++i) {
        int n = nb + ty + i * 8;
        wh[(size_t)n * E_ + kb + tx] = __float2half(t[tx][ty + i * 8]);
    }
}

// ---------------------------------------------------------------------------
// fp16 GEMM core: C = (Ah [+ Al]) * Wh^T + bias  (validated R16)
//   BK=32, 2-stage cp.async. TERMS=2: stage 24KB; TERMS=1: stage 16KB.
// OUT: 0 = fp32 C, 1 = fp16 single (Ch, output scaled by oscale)
// ---------------------------------------------------------------------------
#define G_TILE  8192
#define GEMM_SMEM (2 * 24576)   // max stage config
#define G_NKC 64   // K / 32

template <int OUT, int TERMS>
__device__ __forceinline__ void gemm_body(
    const __half* __restrict__ Ah, const __half* __restrict__ Al,
    const __half* __restrict__ Wh,
    const float* __restrict__ bias, float oscale, float* __restrict__ C,
    __half* __restrict__ Ch,
    char* smc, int bx, int by)
{
    constexpr uint32_t STAGE = (TERMS == 2) ? 24576u : 16384u;
    constexpr uint32_t WOFF  = (TERMS == 2) ? 16384u : 8192u;

    const uint32_t sb = smem_u32(smc);
    const int tid  = threadIdx.x;
    const int wid  = tid >> 5;
    const int lane = tid & 31;

    const int warpM = (wid >> 2) * 64;
    const int warpN = (wid & 3) * 32;

    const size_t aRow0 = (size_t)by * 128;
    const size_t bRow0 = (size_t)bx * 128;

    float acc[4][4][4];
    #pragma unroll
    for (int mi = 0; mi < 4; ++mi)
        #pragma unroll
        for (int ni = 0; ni < 4; ++ni)
            #pragma unroll
            for (int j = 0; j < 4; ++j) acc[mi][ni][j] = 0.f;

    const uint32_t aRowL = warpM + (lane & 15);
    const uint32_t aColL = (lane >> 4) * 8;
    const uint32_t bRowL = warpN + (lane & 7);
    const uint32_t bColL = ((lane >> 3) & 1) * 8;

    const int ldR0 = tid >> 2;
    const int ldS  = tid & 3;

    auto load_stage = [&](int kc, int st) {
        const int k0 = kc * 32;
        const uint32_t base = sb + st * STAGE;
        #pragma unroll
        for (int it = 0; it < 2; ++it) {
            const int r = ldR0 + it * 64;
            const uint32_t o = SMEM_SWIZZLE_64B((uint32_t)(r * 64 + ldS * 16));
            const size_t gA = (aRow0 + r) * E_ + k0 + ldS * 8;
            const size_t gB = (bRow0 + r) * E_ + k0 + ldS * 8;
            cpasync16(base + o, Ah + gA);
            if constexpr (TERMS == 2) cpasync16(base + G_TILE + o, Al + gA);
            cpasync16(base + WOFF + o, Wh + gB);
        }
    };

    load_stage(0, 0); CP_COMMIT();
    load_stage(1, 1); CP_COMMIT();

    for (int kc = 0; kc < G_NKC; ++kc) {
        if (kc == G_NKC - 1) { CP_WAIT0(); } else { CP_WAIT1(); }
        __syncthreads();

        const uint32_t SAH = sb + (kc & 1) * STAGE;
        const uint32_t SAL = SAH + G_TILE;
        const uint32_t SBH = SAH + WOFF;

        #pragma unroll
        for (int ks = 0; ks < 2; ++ks) {
            const uint32_t kb = ks * 16;
            uint32_t ah[4][4], al[4][4], bh[4][2];
            #pragma unroll
            for (int mi = 0; mi < 4; ++mi) {
                uint32_t off = (aRowL + mi * 16) * 64 + (kb + aColL) * 2;
                off = SMEM_SWIZZLE_64B(off);
                ldsm_x4(ah[mi], SAH + off);
                if constexpr (TERMS == 2) ldsm_x4(al[mi], SAL + off);
            }
            #pragma unroll
            for (int ni = 0; ni < 4; ++ni) {
                uint32_t off = (bRowL + ni * 8) * 64 + (kb + bColL) * 2;
                off = SMEM_SWIZZLE_64B(off);
                ldsm_x2(bh[ni], SBH + off);
            }
            #pragma unroll
            for (int mi = 0; mi < 4; ++mi)
                #pragma unroll
                for (int ni = 0; ni < 4; ++ni) {
                    mma16816h(acc[mi][ni], ah[mi], bh[ni]);
                    if constexpr (TERMS == 2)
                        mma16816h(acc[mi][ni], al[mi], bh[ni]);
                }
        }
        __syncthreads();
        if (kc + 2 < G_NKC) { load_stage(kc + 2, kc & 1); CP_COMMIT(); }
    }

    const int rQuad = lane >> 2;
    const int cPair = (lane & 3) * 2;
    #pragma unroll
    for (int mi = 0; mi < 4; ++mi) {
        #pragma unroll
        for (int ni = 0; ni < 4; ++ni) {
            int row = by * 128 + warpM + mi * 16 + rQuad;
            int col = bx * 128 + warpN + ni * 8 + cPair;
            float b0 = bias[col], b1 = bias[col + 1];
            float o00 = acc[mi][ni][0] + b0, o01 = acc[mi][ni][1] + b1;
            float o10 = acc[mi][ni][2] + b0, o11 = acc[mi][ni][3] + b1;
            if constexpr (OUT == 1) {
                o00 *= oscale; o01 *= oscale; o10 *= oscale; o11 *= oscale;
                size_t i0 = ((size_t)row * E_ + col) >> 1;
                size_t i1 = ((size_t)(row + 8) * E_ + col) >> 1;
                ((uint32_t*)Ch)[i0] = packhf(o00, o01);
                ((uint32_t*)Ch)[i1] = packhf(o10, o11);
            } else {
                *(float2*)(C + (size_t)row * E_ + col)       = make_float2(o00, o01);
                *(float2*)(C + (size_t)(row + 8) * E_ + col) = make_float2(o10, o11);
            }
        }
    }
}

// Batched projection GEMM: z=0 Q (2-term, pre-scaled), z=1 K (1-term), z=2 V (1-term)
__global__ void __launch_bounds__(256, 2) gemm_proj3_kernel(
    const __half* __restrict__ AhAll, const __half* __restrict__ AlQ,
    const __half* __restrict__ WhAll,
    const float* __restrict__ b0, const float* __restrict__ b1,
    const float* __restrict__ b2,
    __half* __restrict__ PhAll)
{
    extern __shared__ char smc[];
    const int p = blockIdx.z;
    if (p == 0) {
        gemm_body<1, 2>(AhAll, AlQ, WhAll, b0, QSCALE, nullptr, PhAll,
                        smc, blockIdx.x, blockIdx.y);
    } else if (p == 1) {
        gemm_body<1, 1>(AhAll + ME, nullptr, WhAll + EE, b1, 1.0f, nullptr,
                        PhAll + ME, smc, blockIdx.x, blockIdx.y);
    } else {
        gemm_body<1, 1>(AhAll + 2 * ME, nullptr, WhAll + 2 * EE, b2, 1.0f, nullptr,
                        PhAll + 2 * ME, smc, blockIdx.x, blockIdx.y);
    }
}

__global__ void __launch_bounds__(256, 2) gemm_out_kernel(
    const __half* __restrict__ Ah, const __half* __restrict__ Al,
    const __half* __restrict__ Wh,
    const float* __restrict__ bias, float* __restrict__ C)
{
    extern __shared__ char smc[];
    gemm_body<0, 2>(Ah, Al, Wh, bias, 1.0f, C, nullptr,
                    smc, blockIdx.x, blockIdx.y);
}

// ---------------------------------------------------------------------------
// Flash attention: fp16 single-term, BM=64, BN=64, 128 threads, log2 softmax.
// R17: Q fragments hoisted to registers; K fragments via paired ldsm_x4.
// Smem: Q 16KB + 2 stages x 32KB = 80KB -> 2 CTA/SM.
// ---------------------------------------------------------------------------
#define FQ     0        // subtiles @0, @8192
#define FKV0   16384
#define KV_STAGE 32768
#define KV_K   0        // subtiles @0, @8192
#define KV_V   16384    // subtiles @16384, @24576 (stage-relative)
#define FL_SMEM (16384 + 2 * 32768)   // 81920

__global__ void __launch_bounds__(128, 2) flash_mma_kernel(
    const __half* __restrict__ Qh, const __half* __restrict__ Kh,
    const __half* __restrict__ Vh,
    __half* __restrict__ Chi, __half* __restrict__ Clo)
{
    extern __shared__ char sm[];
    const uint32_t sb = smem_u32(sm);

    const int qt = blockIdx.x, h = blockIdx.y, b = blockIdx.z;
    const int tid = threadIdx.x, w = tid >> 5, lane = tid & 31;

    const size_t qrow0 = (size_t)b * S_ + qt * 64;
    const size_t hcol = (size_t)h * D_;

    auto load_kv = [&](int kt, int st) {
        const size_t krow0 = (size_t)b * S_ + kt * 64;
        const uint32_t base = sb + FKV0 + st * KV_STAGE;
        #pragma unroll
        for (int it = 0; it < 8; ++it) {
            int idx = tid + it * 128;      // 0..1023 chunks of 16B
            int r = idx >> 4, s = idx & 15;
            uint32_t off = (uint32_t)(s >> 3) * 8192 +
                           SMEM_SWIZZLE_128B((uint32_t)(r * 128 + (s & 7) * 16));
            const size_t g = (krow0 + r) * E_ + hcol + s * 8;
            cpasync16(base + KV_K + off, Kh + g);
            cpasync16(base + KV_V + off, Vh + g);
        }
    };

    load_kv(0, 0); CP_COMMIT();
    load_kv(1, 1); CP_COMMIT();

    // Q fill: [64][128] fp16 (already scaled by SCALE*log2e)
    #pragma unroll
    for (int it = 0; it < 8; ++it) {
        int idx = tid + it * 128;
        int r = idx >> 4, s = idx & 15;
        uint32_t off = (uint32_t)(s >> 3) * 8192 +
                       SMEM_SWIZZLE_128B((uint32_t)(r * 128 + (s & 7) * 16));
        const size_t g = (qrow0 + r) * E_ + hcol + s * 8;
        *(uint4*)(sm + FQ + off) = *(const uint4*)(Qh + g);
    }
    __syncthreads();

    // Hoist Q fragments into registers (invariant across all kv iterations)
    const uint32_t aRowL = w * 16 + (lane & 15);
    const uint32_t aColL = (lane >> 4) * 8;
    uint32_t qfrag[2][4][4];
    #pragma unroll
    for (int half = 0; half < 2; ++half)
        #pragma unroll
        for (int ks = 0; ks < 4; ++ks) {
            uint32_t aoff = SMEM_SWIZZLE_128B(aRowL * 128 + (ks * 16 + aColL) * 2);
            ldsm_x4(qfrag[half][ks], sb + FQ + half * 8192 + aoff);
        }

    float oacc[16][4];
    #pragma unroll
    for (int f = 0; f < 16; ++f)
        #pragma unroll
        for (int j = 0; j < 4; ++j) oacc[f][j] = 0.f;
    float m0 = -1e30f, m1 = -1e30f, l0 = 0.f, l1 = 0.f;

    // K x4-paired lane addressing (validated R10)
    const uint32_t bRowL4 = (lane & 7) + ((lane >> 4) << 3);
    const uint32_t bColL = ((lane >> 3) & 1) * 8;
    const uint32_t vR = lane & 7, vM = lane >> 3;

    for (int kt = 0; kt < 32; ++kt) {
        if (kt == 31) { CP_WAIT0(); } else { CP_WAIT1(); }
        __syncthreads();
        const uint32_t kvb = sb + FKV0 + (kt & 1) * KV_STAGE;

        // ---- S(log2) = Qs K^T : 16x64 per warp, K paired x4 ----
        float sacc[8][4];
        #pragma unroll
        for (int ni = 0; ni < 8; ++ni)
            #pragma unroll
            for (int j = 0; j < 4; ++j) sacc[ni][j] = 0.f;

        #pragma unroll
        for (int half = 0; half < 2; ++half) {
            #pragma unroll
            for (int ks = 0; ks < 4; ++ks) {
                const uint32_t kb = ks * 16;
                #pragma unroll
                for (int nip = 0; nip < 4; ++nip) {
                    uint32_t bh4[4];
                    uint32_t boff = SMEM_SWIZZLE_128B((bRowL4 + nip * 16) * 128 + (kb + bColL) * 2);
                    ldsm_x4(bh4, kvb + KV_K + half * 8192 + boff);
                    mma16816h(sacc[2*nip],     qfrag[half][ks], bh4);
                    mma16816h(sacc[2*nip + 1], qfrag[half][ks], bh4 + 2);
                }
            }
        }

        // ---- online softmax (log2 domain) ----
        float mx0 = -1e30f, mx1 = -1e30f;
        #pragma unroll
        for (int ni = 0; ni < 8; ++ni) {
            mx0 = fmaxf(mx0, fmaxf(sacc[ni][0], sacc[ni][1]));
            mx1 = fmaxf(mx1, fmaxf(sacc[ni][2], sacc[ni][3]));
        }
        mx0 = fmaxf(mx0, __shfl_xor_sync(0xffffffffu, mx0, 1));
        mx0 = fmaxf(mx0, __shfl_xor_sync(0xffffffffu, mx0, 2));
        mx1 = fmaxf(mx1, __shfl_xor_sync(0xffffffffu, mx1, 1));
        mx1 = fmaxf(mx1, __shfl_xor_sync(0xffffffffu, mx1, 2));
        const float mn0 = fmaxf(m0, mx0), mn1 = fmaxf(m1, mx1);
        const float al0 = ex2f(m0 - mn0), al1 = ex2f(m1 - mn1);
        m0 = mn0; m1 = mn1;

        uint32_t ph[8][2];
        float ls0 = 0.f, ls1 = 0.f;
        #pragma unroll
        for (int ni = 0; ni < 8; ++ni) {
            float p00 = ex2f(sacc[ni][0] - mn0);
            float p01 = ex2f(sacc[ni][1] - mn0);
            float p10 = ex2f(sacc[ni][2] - mn1);
            float p11 = ex2f(sacc[ni][3] - mn1);
            ls0 += p00 + p01;
            ls1 += p10 + p11;
            ph[ni][0] = packhf(p00, p01);
            ph[ni][1] = packhf(p10, p11);
        }
        ls0 += __shfl_xor_sync(0xffffffffu, ls0, 1);
        ls0 += __shfl_xor_sync(0xffffffffu, ls0, 2);
        ls1 += __shfl_xor_sync(0xffffffffu, ls1, 1);
        ls1 += __shfl_xor_sync(0xffffffffu, ls1, 2);
        l0 = l0 * al0 + ls0;
        l1 = l1 * al1 + ls1;

        #pragma unroll
        for (int f = 0; f < 16; ++f) {
            oacc[f][0] *= al0; oacc[f][1] *= al0;
            oacc[f][2] *= al1; oacc[f][3] *= al1;
        }

        // ---- O += P V : P is 16x64 -> 4 k-fragments ----
        #pragma unroll
        for (int kf = 0; kf < 4; ++kf) {
            uint32_t aPh[4] = { ph[2*kf][0], ph[2*kf][1], ph[2*kf+1][0], ph[2*kf+1][1] };
            #pragma unroll
            for (int nd = 0; nd < 8; ++nd) {
                const uint32_t sub = (nd >> 2) * 8192;
                const uint32_t dd = (nd & 3) * 16;
                const uint32_t kvr = kf * 16 + (vM & 1) * 8 + vR;   // 0..63
                const uint32_t dc = dd + (vM >> 1) * 8;
                const uint32_t voff = SMEM_SWIZZLE_128B(kvr * 128 + dc * 2);
                uint32_t bh4[4];
                ldsm_x4t(bh4, kvb + KV_V + sub + voff);
                mma16816h(oacc[2*nd],     aPh, bh4);
                mma16816h(oacc[2*nd + 1], aPh, bh4 + 2);
            }
        }

        __syncthreads();
        if (kt + 2 < 32) { load_kv(kt + 2, kt & 1); CP_COMMIT(); }
    }

    // ---- finalize: fp16 split context (feeds out-GEMM) ----
    const float inv0 = 1.f / l0, inv1 = 1.f / l1;
    const int rQuad = lane >> 2, cPair = (lane & 3) * 2;
    const size_t row0 = qrow0 + w * 16 + rQuad;
    #pragma unroll
    for (int f = 0; f < 16; ++f) {
        int d = f * 8 + cPair;
        float o00 = oacc[f][0] * inv0, o01 = oacc[f][1] * inv0;
        float o10 = oacc[f][2] * inv1, o11 = oacc[f][3] * inv1;
        size_t i0 = (row0 * E_ + hcol + d) >> 1;
        size_t i1 = ((row0 + 8) * E_ + hcol + d) >> 1;
        uint32_t h0 = packhf(o00, o01);
        uint32_t h1 = packhf(o10, o11);
        ((uint32_t*)Chi)[i0] = h0;
        ((uint32_t*)Chi)[i1] = h1;
        ((uint32_t*)Clo)[i0] = packhf(o00 - lohf(h0), o01 - hihf(h0));
        ((uint32_t*)Clo)[i1] = packhf(o10 - lohf(h1), o11 - hihf(h1));
    }
}

// ---------------------------------------------------------------------------
extern "C" void kernel_launch(void* const* d_in, const int* in_sizes, int n_in,
                              void* d_out, int out_size)
{
    const float* query  = (const float*)d_in[0];
    const float* key_in = (const float*)d_in[1];
    const float* value  = (const float*)d_in[2];
    const float* Wq = (const float*)d_in[3];
    const float* bq = (const float*)d_in[4];
    const float* Wk = (const float*)d_in[5];
    const float* bk = (const float*)d_in[6];
    const float* Wv = (const float*)d_in[7];
    const float* bv = (const float*)d_in[8];
    const float* Wo = (const float*)d_in[9];
    const float* bo = (const float*)d_in[10];
    float* out = (float*)d_out;

    __half *Ah, *Al, *Wh, *Ph, *Chi, *Clo;
    cudaGetSymbolAddress((void**)&Ah,  g_Ah);
    cudaGetSymbolAddress((void**)&Al,  g_Al);
    cudaGetSymbolAddress((void**)&Wh,  g_Wh);
    cudaGetSymbolAddress((void**)&Ph,  g_Ph);
    cudaGetSymbolAddress((void**)&Chi, g_Chi);
    cudaGetSymbolAddress((void**)&Clo, g_Clo);

    cudaFuncSetAttribute(flash_mma_kernel,
                         cudaFuncAttributeMaxDynamicSharedMemorySize, FL_SMEM);
    cudaFuncSetAttribute(gemm_proj3_kernel,
                         cudaFuncAttributeMaxDynamicSharedMemorySize, GEMM_SMEM);
    cudaFuncSetAttribute(gemm_out_kernel,
                         cudaFuncAttributeMaxDynamicSharedMemorySize, GEMM_SMEM);

    const dim3 cw(E_ / 32, E_ / 32, 4);
    const dim3 sa((MROWS * E_ / 4) / 256, 1, 3);
    const dim3 g3(E_ / 128, MROWS / 128, 3);
    const dim3 gg(E_ / 128, MROWS / 128);
    const dim3 fg(S_ / 64, H_, B_);

    convW4_kernel<<<cw, 256>>>(Wq, Wk, Wv, Wo, Wh);
    splitA3_kernel<<<sa, 256>>>(query, key_in, value, Ah, Al);

    // Q (2-term, pre-scaled), K, V (1-term) projections in one launch
    gemm_proj3_kernel<<<g3, 256, GEMM_SMEM>>>(Ah, Al, Wh, bq, bk, bv, Ph);

    // Attention (fp16 single-term, log2-domain softmax) -> fp16 split context
    flash_mma_kernel<<<fg, 128, FL_SMEM>>>(
        Ph + 0 * ME, Ph + 1 * ME, Ph + 2 * ME, Chi, Clo);

    // Output projection (2-term fp16) -> fp32 out
    gemm_out_kernel<<<gg, 256, GEMM_SMEM>>>(Chi, Clo, Wh + 3 * EE, bo, out);
}